// round 8
// baseline (speedup 1.0000x reference)
#include <cuda_runtime.h>
#include <cuda_bf16.h>
#include <cstdint>

#define HDIM  1024
#define BATCH 256
#define TLEN  512
#define NCTA  128
#define NTHR  512

// ---- dynamic smem layout (bytes) ----
#define RSB2   4160            // W row stride (bytes): 4096 + 64 -> quarter-warp conflict-free LDS.128
#define O_W2   0               // 32 * 4160 = 133120
#define O_P    133120          // float[4][64][36] = 36864
#define O_XS   169984          // float[64]
#define O_BIAS 170240          // float[32]
#define O_WIH  170368          // float[32]
#define O_WOUT 170496          // float[32]
#define O_RED  170624          // float[256]
#define SMEM_BYTES 171648

// -------- device scratch --------
__device__ __align__(16) uint32_t g_hpk3[3][BATCH * HDIM];  // lo16=hi-bf16, hi16=lo-bf16
__device__ float g_xpart[2][32][BATCH];
__device__ float g_out[BATCH * TLEN];
__device__ float g_feat[BATCH * 3];
__device__ float g_lossnum;
__device__ unsigned g_cntF;
__device__ volatile unsigned g_relF;
__device__ unsigned g_flag[4][32];   // per (m-group, n-tile) publication counter (monotonic)

// -------- helpers --------
__device__ __forceinline__ uint32_t prmt(uint32_t a, uint32_t b, uint32_t s) {
    uint32_t d;
    asm("prmt.b32 %0, %1, %2, %3;" : "=r"(d) : "r"(a), "r"(b), "r"(s));
    return d;
}
__device__ __forceinline__ void mma_bf16(float c[4], uint32_t a0, uint32_t a1,
                                         uint32_t a2, uint32_t a3,
                                         uint32_t b0, uint32_t b1) {
    asm volatile(
        "mma.sync.aligned.m16n8k16.row.col.f32.bf16.bf16.f32 "
        "{%0,%1,%2,%3}, {%4,%5,%6,%7}, {%8,%9}, {%0,%1,%2,%3};"
        : "+f"(c[0]), "+f"(c[1]), "+f"(c[2]), "+f"(c[3])
        : "r"(a0), "r"(a1), "r"(a2), "r"(a3), "r"(b0), "r"(b1));
}
__device__ __forceinline__ uint32_t packsplit(float v) {
    __nv_bfloat16 hi = __float2bfloat16(v);
    __nv_bfloat16 lo = __float2bfloat16(v - __bfloat162float(hi));
    return (uint32_t)__bfloat16_as_ushort(hi) | ((uint32_t)__bfloat16_as_ushort(lo) << 16);
}
__device__ __forceinline__ float unpacksum(uint32_t w) {
    return __bfloat162float(__ushort_as_bfloat16((unsigned short)(w & 0xffffu))) +
           __bfloat162float(__ushort_as_bfloat16((unsigned short)(w >> 16)));
}
__device__ __forceinline__ unsigned ld_acq(const unsigned* p) {
    unsigned v;
    asm volatile("ld.global.acquire.gpu.u32 %0, [%1];" : "=r"(v) : "l"(p) : "memory");
    return v;
}
__device__ __forceinline__ void st_rel(unsigned* p, unsigned v) {
    asm volatile("st.global.release.gpu.u32 [%0], %1;" :: "l"(p), "r"(v) : "memory");
}
__device__ __forceinline__ void waitf(const unsigned* p, unsigned tgt) {
    while ((int)(ld_acq(p) - tgt) < 0) { }
}

// -------- full-grid barrier (monotonic epochs, replay-safe) --------
__device__ __forceinline__ void gbarF(unsigned& ep) {
    __syncthreads();
    if (threadIdx.x == 0) {
        ep++;
        __threadfence();
        unsigned old = atomicAdd(&g_cntF, 1u);
        if (old == ep * NCTA - 1u) {
            __threadfence();
            g_relF = ep;
        } else {
            while ((int)(g_relF - ep) < 0) { __nanosleep(32); }
            __threadfence();
        }
    }
    __syncthreads();
}

extern "C" __global__ void __launch_bounds__(NTHR, 1) persist_mma(
    const float* __restrict__ input, const int* __restrict__ seqlen,
    const float* __restrict__ Wih_e, const float* __restrict__ Whh_e,
    const float* __restrict__ bih_e, const float* __restrict__ bhh_e,
    const float* __restrict__ Wenc,  const float* __restrict__ benc,
    const float* __restrict__ Wdec,  const float* __restrict__ bdec,
    const float* __restrict__ Wih_d, const float* __restrict__ Whh_d,
    const float* __restrict__ bih_d, const float* __restrict__ bhh_d,
    const float* __restrict__ Wout,  const float* __restrict__ bout,
    float* __restrict__ dout, int out_size)
{
    extern __shared__ __align__(16) char sc[];
    float* Psm     = (float*)(sc + O_P);
    float* xs      = (float*)(sc + O_XS);
    float* bias_sh = (float*)(sc + O_BIAS);
    float* wih_sh  = (float*)(sc + O_WIH);
    float* wout_sh = (float*)(sc + O_WOUT);
    float* red_f   = (float*)(sc + O_RED);

    const int tid  = threadIdx.x;
    const int wid  = tid >> 5;
    const int lane = tid & 31;
    const int g    = lane >> 2;
    const int tg   = lane & 3;
    const int kw   = wid & 3;       // K-split 0..3 (256 each)
    const int wq   = wid >> 2;      // m-quarter 0..3
    const int bx   = blockIdx.x;
    const int nt   = bx & 31;
    const int mt   = bx >> 5;
    const int n0   = nt * 32;
    const int m0   = mt * 64;
    const float bout0 = bout[0];

    unsigned epF = g_relF;
    // flag base: my own flag (only I publish it); uniform across run start
    const unsigned fbase = ld_acq(&g_flag[mt][nt]);
    const unsigned* fgrp = &g_flag[mt][0];

    // ---- init: zero h buf 0 (state 0), loss ----
    {
        int gtid = bx * NTHR + tid;                 // 65536 threads x uint4
        *(uint4*)(g_hpk3[0] + gtid * 4) = make_uint4(0, 0, 0, 0);
        if (gtid == 0) g_lossnum = 0.f;
    }
    gbarF(epF);

    // ================= two RNN phases =================
    for (int phase = 0; phase < 2; phase++) {
        const float* Whh = phase ? Whh_d : Whh_e;
        const float* Wih = phase ? Wih_d : Wih_e;
        const float* bih = phase ? bih_d : bih_e;
        const float* bhh = phase ? bhh_d : bhh_e;

        // ---- preload W slice: per lane-k16 packed uint4 {hi(k,k+1), hi(k+8,k+9), lo(k,k+1), lo(k+8,k+9)} ----
        for (int i = tid; i < 32 * HDIM; i += NTHR) {
            int nn = i >> 10, k = i & 1023;
            float w = Whh[(size_t)(n0 + nn) * HDIM + k];
            __nv_bfloat16 hi = __float2bfloat16(w);
            __nv_bfloat16 lo = __float2bfloat16(w - __bfloat162float(hi));
            int k16g = k >> 4, tgs = (k & 7) >> 1, half = (k >> 3) & 1, b = k & 1;
            char* base = sc + O_W2 + nn * RSB2 + k16g * 64 + tgs * 16 + half * 4 + b * 2;
            *(__nv_bfloat16*)base       = hi;
            *(__nv_bfloat16*)(base + 8) = lo;
        }
        if (tid < 32) {
            bias_sh[tid] = bih[n0 + tid] + bhh[n0 + tid];
            wih_sh[tid]  = Wih[n0 + tid];
            wout_sh[tid] = Wout[n0 + tid];
        }
        __syncthreads();

        for (int t = 0; t < TLEN; t++) {
            const int s = phase * TLEN + t;          // global step 0..1023
            const uint2* hp = (const uint2*)g_hpk3[s % 3];
            uint32_t* hw = g_hpk3[(s + 1) % 3];
            const unsigned tgt = fbase + (unsigned)s;

            // ---- MMA mainloop: warp m16 x n32 over K=256, flag-gated A prefetch ----
            float acc[4][4];
#pragma unroll
            for (int nb = 0; nb < 4; nb++)
#pragma unroll
                for (int q = 0; q < 4; q++) acc[nb][q] = 0.f;

            const int r0 = m0 + wq * 16 + g;
            const size_t rowbase = (size_t)r0 * HDIM;
            uint2 cu[4], nu[4];
            waitf(fgrp + kw * 8, tgt);               // chunk 0 of this K-split
            {
                size_t base = rowbase + kw * 256 + tg * 2;
                cu[0] = __ldcg(hp + (base >> 1));
                cu[1] = __ldcg(hp + ((base + 8 * HDIM) >> 1));
                cu[2] = __ldcg(hp + ((base + 8) >> 1));
                cu[3] = __ldcg(hp + ((base + 8 * HDIM + 8) >> 1));
            }
#pragma unroll 4
            for (int k16 = 0; k16 < 16; k16++) {
                const int kk = kw * 256 + k16 * 16;
                if (k16 < 15) {
                    if (k16 & 1) waitf(fgrp + kw * 8 + ((k16 + 1) >> 1), tgt);
                    size_t base = rowbase + kk + 16 + tg * 2;
                    nu[0] = __ldcg(hp + (base >> 1));
                    nu[1] = __ldcg(hp + ((base + 8 * HDIM) >> 1));
                    nu[2] = __ldcg(hp + ((base + 8) >> 1));
                    nu[3] = __ldcg(hp + ((base + 8 * HDIM + 8) >> 1));
                }
                uint32_t ah[4], al[4];
#pragma unroll
                for (int j = 0; j < 4; j++) {
                    ah[j] = prmt(cu[j].x, cu[j].y, 0x5410);
                    al[j] = prmt(cu[j].x, cu[j].y, 0x7632);
                }
                const char* wrow = sc + O_W2 + (size_t)g * RSB2 + (kw * 16 + k16) * 64 + tg * 16;
#pragma unroll
                for (int nb = 0; nb < 4; nb++) {
                    uint4 v = *(const uint4*)(wrow + (size_t)nb * 8 * RSB2);
                    mma_bf16(acc[nb], ah[0], ah[1], ah[2], ah[3], v.x, v.y);
                    mma_bf16(acc[nb], ah[0], ah[1], ah[2], ah[3], v.z, v.w);
                    mma_bf16(acc[nb], al[0], al[1], al[2], al[3], v.x, v.y);
                }
#pragma unroll
                for (int j = 0; j < 4; j++) cu[j] = nu[j];
            }

            // ---- store k-split partials ----
            {
                int mrow = wq * 16 + g;
#pragma unroll
                for (int nb = 0; nb < 4; nb++) {
                    int col = nb * 8 + tg * 2;
                    *(float2*)&Psm[(kw * 64 + mrow) * 36 + col]     = make_float2(acc[nb][0], acc[nb][1]);
                    *(float2*)&Psm[(kw * 64 + mrow + 8) * 36 + col] = make_float2(acc[nb][2], acc[nb][3]);
                }
            }
            __syncthreads();   // all flag-waits done => all step-(s-1) epilogues visible

            // ---- per-row scalar x ----
            if (tid < 64) {
                float xv = 0.f;
                int row = m0 + tid;
                if (phase == 0) {
                    xv = input[(size_t)row * TLEN + t];
                } else if (t > 0) {
                    float sx = 0.f;
                    const float* xp = &g_xpart[(t - 1) & 1][0][row];
#pragma unroll
                    for (int j = 0; j < 32; j++) sx += __ldcg(xp + j * BATCH);
                    xv = sx + bout0;
                    if (nt == 0) g_out[(size_t)row * TLEN + (t - 1)] = xv;
                }
                xs[tid] = xv;
            }
            __syncthreads();

            // ---- epilogue: reduce partials, bias + x*Wih, tanh, pack, store ----
            {
                int m = tid >> 3, c4 = (tid & 7) * 4;
                float s0 = 0.f, s1 = 0.f, s2 = 0.f, s3 = 0.f;
#pragma unroll
                for (int kwi = 0; kwi < 4; kwi++) {
                    float4 q = *(const float4*)&Psm[(kwi * 64 + m) * 36 + c4];
                    s0 += q.x; s1 += q.y; s2 += q.z; s3 += q.w;
                }
                float xv = xs[m];
                float hv[4];
                hv[0] = tanhf(s0 + bias_sh[c4]     + xv * wih_sh[c4]);
                hv[1] = tanhf(s1 + bias_sh[c4 + 1] + xv * wih_sh[c4 + 1]);
                hv[2] = tanhf(s2 + bias_sh[c4 + 2] + xv * wih_sh[c4 + 2]);
                hv[3] = tanhf(s3 + bias_sh[c4 + 3] + xv * wih_sh[c4 + 3]);
                *(uint4*)(hw + (size_t)(m0 + m) * HDIM + n0 + c4) =
                    make_uint4(packsplit(hv[0]), packsplit(hv[1]),
                               packsplit(hv[2]), packsplit(hv[3]));
                if (phase == 1) {
                    float po = hv[0] * wout_sh[c4]     + hv[1] * wout_sh[c4 + 1]
                             + hv[2] * wout_sh[c4 + 2] + hv[3] * wout_sh[c4 + 3];
                    po += __shfl_xor_sync(0xffffffffu, po, 1);
                    po += __shfl_xor_sync(0xffffffffu, po, 2);
                    po += __shfl_xor_sync(0xffffffffu, po, 4);
                    if ((tid & 7) == 0) g_xpart[t & 1][nt][m0 + m] = po;
                }
            }
            __threadfence();
            __syncthreads();
            if (tid == 0) st_rel((unsigned*)&g_flag[mt][nt], fbase + (unsigned)s + 1u);
        } // t

        gbarF(epF);   // all CTAs done with phase

        if (phase == 0) {
            // ---- features = sigmoid(hT @ Wenc^T + benc); hT = state 512 = buf 2 ----
            int d = bx * 16 + wid;
            if (d < 768) {
                int b = d / 3, e = d - 3 * b;
                const uint32_t* hpk = g_hpk3[2] + (size_t)b * HDIM;
                const float* wp = Wenc + (size_t)e * HDIM;
                float s = 0.f;
                for (int k = lane * 4; k < HDIM; k += 128) {
                    uint4 w4 = __ldcg((const uint4*)(hpk + k));
                    s = fmaf(unpacksum(w4.x), wp[k],     s);
                    s = fmaf(unpacksum(w4.y), wp[k + 1], s);
                    s = fmaf(unpacksum(w4.z), wp[k + 2], s);
                    s = fmaf(unpacksum(w4.w), wp[k + 3], s);
                }
#pragma unroll
                for (int o = 16; o; o >>= 1) s += __shfl_xor_sync(0xffffffffu, s, o);
                if (lane == 0) g_feat[b * 3 + e] = 1.f / (1.f + expf(-(s + benc[e])));
            }
            gbarF(epF);
            // ---- h0 = features @ Wdec^T + bdec -> buf 2 (decoder state 512) ----
#pragma unroll
            for (int r = 0; r < 4; r++) {
                int i = bx * 2048 + r * NTHR + tid;
                int b = i >> 10, j = i & 1023;
                float v = bdec[j] + __ldcg(&g_feat[b * 3])     * Wdec[j * 3]
                                  + __ldcg(&g_feat[b * 3 + 1]) * Wdec[j * 3 + 1]
                                  + __ldcg(&g_feat[b * 3 + 2]) * Wdec[j * 3 + 2];
                g_hpk3[2][i] = packsplit(v);
            }
            gbarF(epF);
        }
    } // phases

    // ---- tail: out[:, 511] = bout + sum xpart[1] ----
    if (bx == 0 && tid < 256) {
        float s = bout0;
#pragma unroll
        for (int j = 0; j < 32; j++) s += __ldcg(&g_xpart[1][j][tid]);
        g_out[(size_t)tid * TLEN + (TLEN - 1)] = s;
    }
    gbarF(epF);

    // ---- masked MSE numerator: 2 rows per CTA ----
    {
        int b = bx * 2 + (tid >> 8), l = tid & 255;
        int L = seqlen[b];
        float s = 0.f;
        for (int tt = l; tt < L; tt += 256) {
            float d = input[(size_t)b * TLEN + tt] - __ldcg(&g_out[(size_t)b * TLEN + tt]);
            s = fmaf(d, d, s);
        }
#pragma unroll
        for (int o = 16; o; o >>= 1) s += __shfl_xor_sync(0xffffffffu, s, o);
        if ((tid & 31) == 0) red_f[wid] = s;
        __syncthreads();
        if (tid == 0) {
            float tot = 0.f;
#pragma unroll
            for (int q = 0; q < 16; q++) tot += red_f[q];
            atomicAdd(&g_lossnum, tot);
        }
        __syncthreads();
    }
    gbarF(epF);

    // ---- finalize loss (CTA 0) ----
    if (bx == 0) {
        if (tid < 256) red_f[tid] = (float)seqlen[tid];
        __syncthreads();
        for (int o = 128; o; o >>= 1) {
            if (tid < o && tid + o < 256) red_f[tid] += red_f[tid + o];
            __syncthreads();
        }
        if (tid == 0 && out_size > 0) dout[0] = g_lossnum / red_f[0];
    }

    // ---- pack (loss | input | output | features) ----
    {
        int chunk = (out_size + NCTA - 1) / NCTA;
        int lo = bx * chunk;
        int hi = lo + chunk; if (hi > out_size) hi = out_size;
        for (int i = lo + tid; i < hi; i += NTHR) {
            if (i == 0) continue;
            int j = i - 1;
            if (j < BATCH * TLEN) { dout[i] = input[j]; continue; }
            j -= BATCH * TLEN;
            if (j < BATCH * TLEN) { dout[i] = __ldcg(&g_out[j]); continue; }
            j -= BATCH * TLEN;
            if (j < BATCH * 3) { dout[i] = __ldcg(&g_feat[j]); continue; }
            dout[i] = 0.f;
        }
    }
}

extern "C" void kernel_launch(void* const* d_in, const int* in_sizes, int n_in,
                              void* d_out, int out_size) {
    const float* input  = (const float*)d_in[0];
    const int*   seqlen = (const int*)d_in[1];
    const float* Wih_e = (const float*)d_in[2];
    const float* Whh_e = (const float*)d_in[3];
    const float* bih_e = (const float*)d_in[4];
    const float* bhh_e = (const float*)d_in[5];
    const float* Wenc  = (const float*)d_in[6];
    const float* benc  = (const float*)d_in[7];
    const float* Wdec  = (const float*)d_in[8];
    const float* bdec  = (const float*)d_in[9];
    const float* Wih_d = (const float*)d_in[10];
    const float* Whh_d = (const float*)d_in[11];
    const float* bih_d = (const float*)d_in[12];
    const float* bhh_d = (const float*)d_in[13];
    const float* Wout  = (const float*)d_in[14];
    const float* bout  = (const float*)d_in[15];

    cudaFuncSetAttribute(persist_mma,
                         cudaFuncAttributeMaxDynamicSharedMemorySize, SMEM_BYTES);
    persist_mma<<<NCTA, NTHR, SMEM_BYTES>>>(
        input, seqlen, Wih_e, Whh_e, bih_e, bhh_e, Wenc, benc,
        Wdec, bdec, Wih_d, Whh_d, bih_d, bhh_d, Wout, bout,
        (float*)d_out, out_size);
}

// round 9
// speedup vs baseline: 1.8311x; 1.8311x over previous
#include <cuda_runtime.h>
#include <cuda_bf16.h>
#include <cstdint>

#define HDIM  1024
#define BATCH 256
#define TLEN  512
#define NCTA  128
#define NTHR  512

// ---- dynamic smem layout (bytes) ----
#define RSB2   4160            // W row stride: 4096 + 64 -> conflict-free LDS.128
#define O_W2   0               // 32 * 4160 = 133120
#define O_P    133120          // float[4][64][36] = 36864
#define O_XS   169984          // float[64]
#define O_BIAS 170240          // float[32]
#define O_WIH  170368          // float[32]
#define O_WOUT 170496          // float[32]
#define O_RED  170624          // float[256]
#define SMEM_BYTES 171648

// -------- device scratch --------
__device__ __align__(16) uint32_t g_hpk[2][BATCH * HDIM];  // lo16=hi-bf16, hi16=lo-bf16
__device__ float g_xpart[2][32][BATCH];
__device__ float g_out[BATCH * TLEN];
__device__ float g_feat[BATCH * 3];
__device__ float g_lossnum;
__device__ unsigned g_cntF;
__device__ unsigned g_relF;
__device__ unsigned g_cntG[4 * 32];            // 128B-padded per m-group
__device__ unsigned g_relG[4 * 32];

// -------- helpers --------
__device__ __forceinline__ uint32_t prmt(uint32_t a, uint32_t b, uint32_t s) {
    uint32_t d;
    asm("prmt.b32 %0, %1, %2, %3;" : "=r"(d) : "r"(a), "r"(b), "r"(s));
    return d;
}
__device__ __forceinline__ void mma_bf16(float c[4], uint32_t a0, uint32_t a1,
                                         uint32_t a2, uint32_t a3,
                                         uint32_t b0, uint32_t b1) {
    asm volatile(
        "mma.sync.aligned.m16n8k16.row.col.f32.bf16.bf16.f32 "
        "{%0,%1,%2,%3}, {%4,%5,%6,%7}, {%8,%9}, {%0,%1,%2,%3};"
        : "+f"(c[0]), "+f"(c[1]), "+f"(c[2]), "+f"(c[3])
        : "r"(a0), "r"(a1), "r"(a2), "r"(a3), "r"(b0), "r"(b1));
}
__device__ __forceinline__ uint32_t packsplit(float v) {
    __nv_bfloat16 hi = __float2bfloat16(v);
    __nv_bfloat16 lo = __float2bfloat16(v - __bfloat162float(hi));
    return (uint32_t)__bfloat16_as_ushort(hi) | ((uint32_t)__bfloat16_as_ushort(lo) << 16);
}
__device__ __forceinline__ float unpacksum(uint32_t w) {
    return __bfloat162float(__ushort_as_bfloat16((unsigned short)(w & 0xffffu))) +
           __bfloat162float(__ushort_as_bfloat16((unsigned short)(w >> 16)));
}
__device__ __forceinline__ float ftanh(float x) {
    float e = __expf(2.0f * x);
    return __fdividef(e - 1.0f, e + 1.0f);
}
__device__ __forceinline__ unsigned ld_acq(const unsigned* p) {
    unsigned v;
    asm volatile("ld.global.acquire.gpu.u32 %0, [%1];" : "=r"(v) : "l"(p) : "memory");
    return v;
}
__device__ __forceinline__ void st_rel(unsigned* p, unsigned v) {
    asm volatile("st.global.release.gpu.u32 [%0], %1;" :: "l"(p), "r"(v) : "memory");
}

// -------- barrier: acq_rel atom arrive + acquire poll (monotonic, replay-safe) --------
__device__ __forceinline__ void gbar(unsigned* cnt, unsigned* rel, unsigned n, unsigned& ep) {
    __syncthreads();
    if (threadIdx.x == 0) {
        ep++;
        unsigned old;
        asm volatile("atom.global.add.acq_rel.gpu.u32 %0, [%1], 1;"
                     : "=r"(old) : "l"(cnt) : "memory");
        if (old == ep * n - 1u) {
            st_rel(rel, ep);
        } else {
            while ((int)(ld_acq(rel) - ep) < 0) { }
        }
    }
    __syncthreads();
}

extern "C" __global__ void __launch_bounds__(NTHR, 1) persist_mma(
    const float* __restrict__ input, const int* __restrict__ seqlen,
    const float* __restrict__ Wih_e, const float* __restrict__ Whh_e,
    const float* __restrict__ bih_e, const float* __restrict__ bhh_e,
    const float* __restrict__ Wenc,  const float* __restrict__ benc,
    const float* __restrict__ Wdec,  const float* __restrict__ bdec,
    const float* __restrict__ Wih_d, const float* __restrict__ Whh_d,
    const float* __restrict__ bih_d, const float* __restrict__ bhh_d,
    const float* __restrict__ Wout,  const float* __restrict__ bout,
    float* __restrict__ dout, int out_size)
{
    extern __shared__ __align__(16) char sc[];
    float* Psm     = (float*)(sc + O_P);
    float* xs      = (float*)(sc + O_XS);
    float* bias_sh = (float*)(sc + O_BIAS);
    float* wih_sh  = (float*)(sc + O_WIH);
    float* wout_sh = (float*)(sc + O_WOUT);
    float* red_f   = (float*)(sc + O_RED);

    const int tid  = threadIdx.x;
    const int wid  = tid >> 5;
    const int lane = tid & 31;
    const int g    = lane >> 2;
    const int tg   = lane & 3;
    const int kw   = wid & 3;       // K-split 0..3 (256 each)
    const int wq   = wid >> 2;      // m-quarter 0..3
    const int bx   = blockIdx.x;
    const int nt   = bx & 31;
    const int mt   = bx >> 5;
    const int n0   = nt * 32;
    const int m0   = mt * 64;
    const float bout0 = bout[0];

    unsigned epF = g_relF;
    unsigned epG = g_relG[mt * 32];
    unsigned* cG = &g_cntG[mt * 32];
    unsigned* rG = &g_relG[mt * 32];

    // ---- init: zero h buf 0, loss ----
    {
        int gtid = bx * NTHR + tid;
        *(uint4*)(g_hpk[0] + gtid * 4) = make_uint4(0, 0, 0, 0);
        if (gtid == 0) g_lossnum = 0.f;
    }
    gbar(&g_cntF, &g_relF, NCTA, epF);

    // ================= two RNN phases =================
    for (int phase = 0; phase < 2; phase++) {
        const float* Whh = phase ? Whh_d : Whh_e;
        const float* Wih = phase ? Wih_d : Wih_e;
        const float* bih = phase ? bih_d : bih_e;
        const float* bhh = phase ? bhh_d : bhh_e;

        // ---- preload W slice: per (nn,k16) 64B block: lane tg uint4 =
        //      {hi(k+2tg,k+2tg+1), hi(k+2tg+8,+9), lo(...), lo(...)} ----
        for (int i = tid; i < 32 * HDIM; i += NTHR) {
            int nn = i >> 10, k = i & 1023;
            float w = Whh[(size_t)(n0 + nn) * HDIM + k];
            __nv_bfloat16 hi = __float2bfloat16(w);
            __nv_bfloat16 lo = __float2bfloat16(w - __bfloat162float(hi));
            int k16g = k >> 4, tgs = (k & 7) >> 1, half = (k >> 3) & 1, b = k & 1;
            char* base = sc + O_W2 + nn * RSB2 + k16g * 64 + tgs * 16 + half * 4 + b * 2;
            *(__nv_bfloat16*)base       = hi;
            *(__nv_bfloat16*)(base + 8) = lo;
        }
        if (tid < 32) {
            bias_sh[tid] = bih[n0 + tid] + bhh[n0 + tid];
            wih_sh[tid]  = Wih[n0 + tid];
            wout_sh[tid] = Wout[n0 + tid];
        }
        __syncthreads();

        for (int t = 0; t < TLEN; t++) {
            const int rp = t & 1;
            const uint2* hp = (const uint2*)g_hpk[rp];

            // ---- per-row scalar x (early: overlaps mainloop latency) ----
            if (tid < 64) {
                float xv = 0.f;
                int row = m0 + tid;
                if (phase == 0) {
                    xv = input[(size_t)row * TLEN + t];
                } else if (t > 0) {
                    float sx = 0.f;
                    const float* xp = &g_xpart[(t - 1) & 1][0][row];
#pragma unroll
                    for (int j = 0; j < 32; j++) sx += __ldcg(xp + j * BATCH);
                    xv = sx + bout0;
                    if (nt == 0) g_out[(size_t)row * TLEN + (t - 1)] = xv;
                }
                xs[tid] = xv;
            }

            // ---- MMA mainloop: warp m16 x n32 over K=256, A double-buffered ----
            float acc[4][4];
#pragma unroll
            for (int nb = 0; nb < 4; nb++)
#pragma unroll
                for (int q = 0; q < 4; q++) acc[nb][q] = 0.f;

            const int r0 = m0 + wq * 16 + g;
            const size_t rowbase = (size_t)r0 * HDIM;
            uint2 cu[4], nu[4];
            {
                size_t base = rowbase + kw * 256 + tg * 2;
                cu[0] = __ldcg(hp + (base >> 1));
                cu[1] = __ldcg(hp + ((base + 8 * HDIM) >> 1));
                cu[2] = __ldcg(hp + ((base + 8) >> 1));
                cu[3] = __ldcg(hp + ((base + 8 * HDIM + 8) >> 1));
            }
#pragma unroll 4
            for (int k16 = 0; k16 < 16; k16++) {
                const int kk = kw * 256 + k16 * 16;
                if (k16 < 15) {
                    size_t base = rowbase + kk + 16 + tg * 2;
                    nu[0] = __ldcg(hp + (base >> 1));
                    nu[1] = __ldcg(hp + ((base + 8 * HDIM) >> 1));
                    nu[2] = __ldcg(hp + ((base + 8) >> 1));
                    nu[3] = __ldcg(hp + ((base + 8 * HDIM + 8) >> 1));
                }
                uint32_t ah[4], al[4];
#pragma unroll
                for (int j = 0; j < 4; j++) {
                    ah[j] = prmt(cu[j].x, cu[j].y, 0x5410);
                    al[j] = prmt(cu[j].x, cu[j].y, 0x7632);
                }
                const char* wrow = sc + O_W2 + (size_t)g * RSB2 + (kw * 16 + k16) * 64 + tg * 16;
#pragma unroll
                for (int nb = 0; nb < 4; nb++) {
                    uint4 v = *(const uint4*)(wrow + (size_t)nb * 8 * RSB2);
                    mma_bf16(acc[nb], ah[0], ah[1], ah[2], ah[3], v.x, v.y);
                    mma_bf16(acc[nb], ah[0], ah[1], ah[2], ah[3], v.z, v.w);
                    mma_bf16(acc[nb], al[0], al[1], al[2], al[3], v.x, v.y);
                }
#pragma unroll
                for (int j = 0; j < 4; j++) cu[j] = nu[j];
            }

            // ---- store k-split partials ----
            {
                int mrow = wq * 16 + g;
#pragma unroll
                for (int nb = 0; nb < 4; nb++) {
                    int col = nb * 8 + tg * 2;
                    *(float2*)&Psm[(kw * 64 + mrow) * 36 + col]     = make_float2(acc[nb][0], acc[nb][1]);
                    *(float2*)&Psm[(kw * 64 + mrow + 8) * 36 + col] = make_float2(acc[nb][2], acc[nb][3]);
                }
            }
            __syncthreads();

            // ---- epilogue: reduce partials, bias + x*Wih, tanh, pack, store ----
            {
                int m = tid >> 3, c4 = (tid & 7) * 4;
                float s0 = 0.f, s1 = 0.f, s2 = 0.f, s3 = 0.f;
#pragma unroll
                for (int kwi = 0; kwi < 4; kwi++) {
                    float4 q = *(const float4*)&Psm[(kwi * 64 + m) * 36 + c4];
                    s0 += q.x; s1 += q.y; s2 += q.z; s3 += q.w;
                }
                float xv = xs[m];
                float hv[4];
                hv[0] = ftanh(s0 + bias_sh[c4]     + xv * wih_sh[c4]);
                hv[1] = ftanh(s1 + bias_sh[c4 + 1] + xv * wih_sh[c4 + 1]);
                hv[2] = ftanh(s2 + bias_sh[c4 + 2] + xv * wih_sh[c4 + 2]);
                hv[3] = ftanh(s3 + bias_sh[c4 + 3] + xv * wih_sh[c4 + 3]);
                *(uint4*)(g_hpk[rp ^ 1] + (size_t)(m0 + m) * HDIM + n0 + c4) =
                    make_uint4(packsplit(hv[0]), packsplit(hv[1]),
                               packsplit(hv[2]), packsplit(hv[3]));
                if (phase == 1) {
                    float po = hv[0] * wout_sh[c4]     + hv[1] * wout_sh[c4 + 1]
                             + hv[2] * wout_sh[c4 + 2] + hv[3] * wout_sh[c4 + 3];
                    po += __shfl_xor_sync(0xffffffffu, po, 1);
                    po += __shfl_xor_sync(0xffffffffu, po, 2);
                    po += __shfl_xor_sync(0xffffffffu, po, 4);
                    if ((tid & 7) == 0) g_xpart[t & 1][nt][m0 + m] = po;
                }
            }
            gbar(cG, rG, 32, epG);    // group-local: deps confined to this m-tile
        } // t  (final h in buf 0)

        gbar(&g_cntF, &g_relF, NCTA, epF);   // cross-group before global reads

        if (phase == 0) {
            // ---- features = sigmoid(hT @ Wenc^T + benc) ----
            int d = bx * 16 + wid;
            if (d < 768) {
                int b = d / 3, e = d - 3 * b;
                const uint32_t* hpk = g_hpk[0] + (size_t)b * HDIM;
                const float* wp = Wenc + (size_t)e * HDIM;
                float s = 0.f;
                for (int k = lane * 4; k < HDIM; k += 128) {
                    uint4 w4 = __ldcg((const uint4*)(hpk + k));
                    s = fmaf(unpacksum(w4.x), wp[k],     s);
                    s = fmaf(unpacksum(w4.y), wp[k + 1], s);
                    s = fmaf(unpacksum(w4.z), wp[k + 2], s);
                    s = fmaf(unpacksum(w4.w), wp[k + 3], s);
                }
#pragma unroll
                for (int o = 16; o; o >>= 1) s += __shfl_xor_sync(0xffffffffu, s, o);
                if (lane == 0) g_feat[b * 3 + e] = 1.f / (1.f + __expf(-(s + benc[e])));
            }
            gbar(&g_cntF, &g_relF, NCTA, epF);
            // ---- h0 = features @ Wdec^T + bdec -> buf 0 packed ----
#pragma unroll
            for (int r = 0; r < 4; r++) {
                int i = bx * 2048 + r * NTHR + tid;
                int b = i >> 10, j = i & 1023;
                float v = bdec[j] + __ldcg(&g_feat[b * 3])     * Wdec[j * 3]
                                  + __ldcg(&g_feat[b * 3 + 1]) * Wdec[j * 3 + 1]
                                  + __ldcg(&g_feat[b * 3 + 2]) * Wdec[j * 3 + 2];
                g_hpk[0][i] = packsplit(v);
            }
            gbar(&g_cntF, &g_relF, NCTA, epF);
        }
    } // phases

    // ---- tail: out[:, 511] = bout + sum xpart[1] ----
    if (bx == 0 && tid < 256) {
        float s = bout0;
#pragma unroll
        for (int j = 0; j < 32; j++) s += __ldcg(&g_xpart[1][j][tid]);
        g_out[(size_t)tid * TLEN + (TLEN - 1)] = s;
    }
    gbar(&g_cntF, &g_relF, NCTA, epF);

    // ---- masked MSE numerator: 2 rows per CTA ----
    {
        int b = bx * 2 + (tid >> 8), l = tid & 255;
        int L = seqlen[b];
        float s = 0.f;
        for (int tt = l; tt < L; tt += 256) {
            float d = input[(size_t)b * TLEN + tt] - __ldcg(&g_out[(size_t)b * TLEN + tt]);
            s = fmaf(d, d, s);
        }
#pragma unroll
        for (int o = 16; o; o >>= 1) s += __shfl_xor_sync(0xffffffffu, s, o);
        if ((tid & 31) == 0) red_f[wid] = s;
        __syncthreads();
        if (tid == 0) {
            float tot = 0.f;
#pragma unroll
            for (int q = 0; q < 16; q++) tot += red_f[q];
            atomicAdd(&g_lossnum, tot);
        }
        __syncthreads();
    }
    gbar(&g_cntF, &g_relF, NCTA, epF);

    // ---- finalize loss (CTA 0) ----
    if (bx == 0) {
        if (tid < 256) red_f[tid] = (float)seqlen[tid];
        __syncthreads();
        for (int o = 128; o; o >>= 1) {
            if (tid < o && tid + o < 256) red_f[tid] += red_f[tid + o];
            __syncthreads();
        }
        if (tid == 0 && out_size > 0) dout[0] = g_lossnum / red_f[0];
    }

    // ---- pack (loss | input | output | features) ----
    {
        int chunk = (out_size + NCTA - 1) / NCTA;
        int lo = bx * chunk;
        int hi = lo + chunk; if (hi > out_size) hi = out_size;
        for (int i = lo + tid; i < hi; i += NTHR) {
            if (i == 0) continue;
            int j = i - 1;
            if (j < BATCH * TLEN) { dout[i] = input[j]; continue; }
            j -= BATCH * TLEN;
            if (j < BATCH * TLEN) { dout[i] = __ldcg(&g_out[j]); continue; }
            j -= BATCH * TLEN;
            if (j < BATCH * 3) { dout[i] = __ldcg(&g_feat[j]); continue; }
            dout[i] = 0.f;
        }
    }
}

extern "C" void kernel_launch(void* const* d_in, const int* in_sizes, int n_in,
                              void* d_out, int out_size) {
    const float* input  = (const float*)d_in[0];
    const int*   seqlen = (const int*)d_in[1];
    const float* Wih_e = (const float*)d_in[2];
    const float* Whh_e = (const float*)d_in[3];
    const float* bih_e = (const float*)d_in[4];
    const float* bhh_e = (const float*)d_in[5];
    const float* Wenc  = (const float*)d_in[6];
    const float* benc  = (const float*)d_in[7];
    const float* Wdec  = (const float*)d_in[8];
    const float* bdec  = (const float*)d_in[9];
    const float* Wih_d = (const float*)d_in[10];
    const float* Whh_d = (const float*)d_in[11];
    const float* bih_d = (const float*)d_in[12];
    const float* bhh_d = (const float*)d_in[13];
    const float* Wout  = (const float*)d_in[14];
    const float* bout  = (const float*)d_in[15];

    cudaFuncSetAttribute(persist_mma,
                         cudaFuncAttributeMaxDynamicSharedMemorySize, SMEM_BYTES);
    persist_mma<<<NCTA, NTHR, SMEM_BYTES>>>(
        input, seqlen, Wih_e, Whh_e, bih_e, bhh_e, Wenc, benc,
        Wdec, bdec, Wih_d, Whh_d, bih_d, bhh_d, Wout, bout,
        (float*)d_out, out_size);
}

// round 10
// speedup vs baseline: 2.4138x; 1.3182x over previous
#include <cuda_runtime.h>
#include <cuda_bf16.h>
#include <cstdint>

#define HDIM  1024
#define BATCH 256
#define TLEN  512
#define NCTA  128
#define NTHR  512

// ---- dynamic smem layout (bytes) ----
#define RSB2   4160            // W row stride: 4096 + 64 -> conflict-free LDS.128
#define O_W2   0               // 32 * 4160 = 133120
#define O_P    133120          // float[4][64][36] = 36864
#define O_XS   169984          // float[64]
#define O_BIAS 170240          // float[32]
#define O_WIH  170368          // float[32]
#define O_WOUT 170496          // float[32]
#define O_RED  170624          // float[256]
#define SMEM_BYTES 171648

// h storage: packed uint32 (lo16=hi-bf16, hi16=lo-bf16), PAIR-PERMUTED within each
// 16-col block: slot(4t+0..3) = logical cols {2t, 2t+1, 2t+8, 2t+9}  (t = 0..3)
// -> lane tg LDG.128 at slot 4*tg yields exactly its m16n8k16 A-fragment columns.
__device__ __align__(16) uint32_t g_hpk[2][BATCH * HDIM];
__device__ float g_xp[2][BATCH][32];     // decoder partial dots, row-major for vector reads
__device__ float g_out[BATCH * TLEN];
__device__ float g_feat[BATCH * 3];
__device__ float g_lossnum;
__device__ unsigned g_cntF;
__device__ unsigned g_relF;
__device__ unsigned g_cntG[4 * 32];      // 128B-padded per m-group
__device__ unsigned g_relG[4 * 32];

// -------- helpers --------
__device__ __forceinline__ uint32_t prmt(uint32_t a, uint32_t b, uint32_t s) {
    uint32_t d;
    asm("prmt.b32 %0, %1, %2, %3;" : "=r"(d) : "r"(a), "r"(b), "r"(s));
    return d;
}
__device__ __forceinline__ void mma_bf16(float c[4], uint32_t a0, uint32_t a1,
                                         uint32_t a2, uint32_t a3,
                                         uint32_t b0, uint32_t b1) {
    asm volatile(
        "mma.sync.aligned.m16n8k16.row.col.f32.bf16.bf16.f32 "
        "{%0,%1,%2,%3}, {%4,%5,%6,%7}, {%8,%9}, {%0,%1,%2,%3};"
        : "+f"(c[0]), "+f"(c[1]), "+f"(c[2]), "+f"(c[3])
        : "r"(a0), "r"(a1), "r"(a2), "r"(a3), "r"(b0), "r"(b1));
}
__device__ __forceinline__ uint32_t packsplit(float v) {
    __nv_bfloat16 hi = __float2bfloat16(v);
    __nv_bfloat16 lo = __float2bfloat16(v - __bfloat162float(hi));
    return (uint32_t)__bfloat16_as_ushort(hi) | ((uint32_t)__bfloat16_as_ushort(lo) << 16);
}
__device__ __forceinline__ float unpacksum(uint32_t w) {
    return __bfloat162float(__ushort_as_bfloat16((unsigned short)(w & 0xffffu))) +
           __bfloat162float(__ushort_as_bfloat16((unsigned short)(w >> 16)));
}
__device__ __forceinline__ float ftanh(float x) {
    float xc = fminf(fmaxf(x, -10.f), 10.f);
    float e = __expf(2.0f * xc);
    return __fdividef(e - 1.0f, e + 1.0f);
}
// logical pos within 16-block -> physical slot
__device__ __forceinline__ int permslot(int p) {
    return 4 * ((p & 7) >> 1) + 2 * ((p >> 3) & 1) + (p & 1);
}
__device__ __forceinline__ unsigned ld_acq(const unsigned* p) {
    unsigned v;
    asm volatile("ld.global.acquire.gpu.u32 %0, [%1];" : "=r"(v) : "l"(p) : "memory");
    return v;
}
__device__ __forceinline__ void st_rel(unsigned* p, unsigned v) {
    asm volatile("st.global.release.gpu.u32 [%0], %1;" :: "l"(p), "r"(v) : "memory");
}

// -------- barrier: acq_rel atom arrive + acquire poll (monotonic, replay-safe) --------
__device__ __forceinline__ void gbar(unsigned* cnt, unsigned* rel, unsigned n, unsigned& ep) {
    __syncthreads();
    if (threadIdx.x == 0) {
        ep++;
        unsigned old;
        asm volatile("atom.global.add.acq_rel.gpu.u32 %0, [%1], 1;"
                     : "=r"(old) : "l"(cnt) : "memory");
        if (old == ep * n - 1u) {
            st_rel(rel, ep);
        } else {
            while ((int)(ld_acq(rel) - ep) < 0) { }
        }
    }
    __syncthreads();
}

extern "C" __global__ void __launch_bounds__(NTHR, 1) persist_mma(
    const float* __restrict__ input, const int* __restrict__ seqlen,
    const float* __restrict__ Wih_e, const float* __restrict__ Whh_e,
    const float* __restrict__ bih_e, const float* __restrict__ bhh_e,
    const float* __restrict__ Wenc,  const float* __restrict__ benc,
    const float* __restrict__ Wdec,  const float* __restrict__ bdec,
    const float* __restrict__ Wih_d, const float* __restrict__ Whh_d,
    const float* __restrict__ bih_d, const float* __restrict__ bhh_d,
    const float* __restrict__ Wout,  const float* __restrict__ bout,
    float* __restrict__ dout, int out_size)
{
    extern __shared__ __align__(16) char sc[];
    float* Psm     = (float*)(sc + O_P);
    float* xs      = (float*)(sc + O_XS);
    float* bias_sh = (float*)(sc + O_BIAS);
    float* wih_sh  = (float*)(sc + O_WIH);
    float* wout_sh = (float*)(sc + O_WOUT);
    float* red_f   = (float*)(sc + O_RED);

    const int tid  = threadIdx.x;
    const int wid  = tid >> 5;
    const int lane = tid & 31;
    const int g    = lane >> 2;
    const int tg   = lane & 3;
    const int kw   = wid & 3;       // K-split 0..3 (256 each)
    const int wq   = wid >> 2;      // m-quarter 0..3
    const int bx   = blockIdx.x;
    const int nt   = bx & 31;
    const int mt   = bx >> 5;
    const int n0   = nt * 32;
    const int m0   = mt * 64;
    const float bout0 = bout[0];

    unsigned epF = g_relF;
    unsigned epG = g_relG[mt * 32];
    unsigned* cG = &g_cntG[mt * 32];
    unsigned* rG = &g_relG[mt * 32];

    // ---- init: zero h buf 0, loss ----
    {
        int gtid = bx * NTHR + tid;
        *(uint4*)(g_hpk[0] + gtid * 4) = make_uint4(0, 0, 0, 0);
        if (gtid == 0) g_lossnum = 0.f;
    }
    gbar(&g_cntF, &g_relF, NCTA, epF);

    // ================= two RNN phases =================
    for (int phase = 0; phase < 2; phase++) {
        const float* Whh = phase ? Whh_d : Whh_e;
        const float* Wih = phase ? Wih_d : Wih_e;
        const float* bih = phase ? bih_d : bih_e;
        const float* bhh = phase ? bhh_d : bhh_e;

        // ---- preload W slice: per (nn,k16) 64B block, lane tg uint4 =
        //      {hi(k+2tg,k+2tg+1), hi(k+2tg+8,+9), lo(...), lo(...)} ----
        for (int i = tid; i < 32 * HDIM; i += NTHR) {
            int nn = i >> 10, k = i & 1023;
            float w = Whh[(size_t)(n0 + nn) * HDIM + k];
            __nv_bfloat16 hi = __float2bfloat16(w);
            __nv_bfloat16 lo = __float2bfloat16(w - __bfloat162float(hi));
            int k16g = k >> 4, tgs = (k & 7) >> 1, half = (k >> 3) & 1, b = k & 1;
            char* base = sc + O_W2 + nn * RSB2 + k16g * 64 + tgs * 16 + half * 4 + b * 2;
            *(__nv_bfloat16*)base       = hi;
            *(__nv_bfloat16*)(base + 8) = lo;
        }
        if (tid < 32) {
            bias_sh[tid] = bih[n0 + tid] + bhh[n0 + tid];
            wih_sh[tid]  = Wih[n0 + tid];
            wout_sh[tid] = Wout[n0 + tid];
        }
        __syncthreads();

        for (int t = 0; t < TLEN; t++) {
            const int rp = t & 1;
            const uint4* hp4 = (const uint4*)g_hpk[rp];

            // ---- per-row scalar x (early: overlaps mainloop latency) ----
            if (tid < 64) {
                float xv = 0.f;
                int row = m0 + tid;
                if (phase == 0) {
                    xv = input[(size_t)row * TLEN + t];
                } else if (t > 0) {
                    const float4* xp = (const float4*)&g_xp[(t - 1) & 1][row][0];
                    float sx = 0.f;
#pragma unroll
                    for (int j = 0; j < 8; j++) {
                        float4 v = __ldcg(xp + j);
                        sx += (v.x + v.y) + (v.z + v.w);
                    }
                    xv = sx + bout0;
                    if (nt == 0) g_out[(size_t)row * TLEN + (t - 1)] = xv;
                }
                xs[tid] = xv;
            }

            // ---- MMA mainloop: warp m16 x n32 over K=256, distance-2 A pipeline ----
            float acc[4][4];
#pragma unroll
            for (int nb = 0; nb < 4; nb++)
#pragma unroll
                for (int q = 0; q < 4; q++) acc[nb][q] = 0.f;

            const int r0 = m0 + wq * 16 + g;
            const size_t b4a = (((size_t)r0 * HDIM) >> 2) + ((kw * 256) >> 2) + tg;
            const size_t b4b = b4a + ((8 * HDIM) >> 2);

            uint4 A[3][2];
            A[0][0] = __ldcg(hp4 + b4a);
            A[0][1] = __ldcg(hp4 + b4b);
            A[1][0] = __ldcg(hp4 + b4a + 4);
            A[1][1] = __ldcg(hp4 + b4b + 4);
#pragma unroll
            for (int c = 0; c < 16; c++) {
                if (c < 14) {
                    A[(c + 2) % 3][0] = __ldcg(hp4 + b4a + (c + 2) * 4);
                    A[(c + 2) % 3][1] = __ldcg(hp4 + b4b + (c + 2) * 4);
                }
                uint4 u = A[c % 3][0], w = A[c % 3][1];
                uint32_t a0h = prmt(u.x, u.y, 0x5410), a2h = prmt(u.z, u.w, 0x5410);
                uint32_t a0l = prmt(u.x, u.y, 0x7632), a2l = prmt(u.z, u.w, 0x7632);
                uint32_t a1h = prmt(w.x, w.y, 0x5410), a3h = prmt(w.z, w.w, 0x5410);
                uint32_t a1l = prmt(w.x, w.y, 0x7632), a3l = prmt(w.z, w.w, 0x7632);
                const char* wrow = sc + O_W2 + (size_t)g * RSB2 + (kw * 16 + c) * 64 + tg * 16;
#pragma unroll
                for (int nb = 0; nb < 4; nb++) {
                    uint4 v = *(const uint4*)(wrow + (size_t)nb * 8 * RSB2);
                    mma_bf16(acc[nb], a0h, a1h, a2h, a3h, v.x, v.y);
                    mma_bf16(acc[nb], a0h, a1h, a2h, a3h, v.z, v.w);
                    mma_bf16(acc[nb], a0l, a1l, a2l, a3l, v.x, v.y);
                }
            }

            // ---- store k-split partials ----
            {
                int mrow = wq * 16 + g;
#pragma unroll
                for (int nb = 0; nb < 4; nb++) {
                    int col = nb * 8 + tg * 2;
                    *(float2*)&Psm[(kw * 64 + mrow) * 36 + col]     = make_float2(acc[nb][0], acc[nb][1]);
                    *(float2*)&Psm[(kw * 64 + mrow + 8) * 36 + col] = make_float2(acc[nb][2], acc[nb][3]);
                }
            }
            __syncthreads();

            // ---- epilogue: reduce partials, bias + x*Wih, tanh, pack, permuted store ----
            {
                int m = tid >> 3, c4 = (tid & 7) * 4;
                float s0 = 0.f, s1 = 0.f, s2 = 0.f, s3 = 0.f;
#pragma unroll
                for (int kwi = 0; kwi < 4; kwi++) {
                    float4 q = *(const float4*)&Psm[(kwi * 64 + m) * 36 + c4];
                    s0 += q.x; s1 += q.y; s2 += q.z; s3 += q.w;
                }
                float xv = xs[m];
                float hv[4];
                hv[0] = ftanh(s0 + bias_sh[c4]     + xv * wih_sh[c4]);
                hv[1] = ftanh(s1 + bias_sh[c4 + 1] + xv * wih_sh[c4 + 1]);
                hv[2] = ftanh(s2 + bias_sh[c4 + 2] + xv * wih_sh[c4 + 2]);
                hv[3] = ftanh(s3 + bias_sh[c4 + 3] + xv * wih_sh[c4 + 3]);
                uint32_t* dst = g_hpk[rp ^ 1] + (size_t)(m0 + m) * HDIM + n0 + (c4 & ~15);
                int sA = permslot(c4 & 15), sB = permslot((c4 + 2) & 15);
                *(uint2*)(dst + sA) = make_uint2(packsplit(hv[0]), packsplit(hv[1]));
                *(uint2*)(dst + sB) = make_uint2(packsplit(hv[2]), packsplit(hv[3]));
                if (phase == 1) {
                    float po = hv[0] * wout_sh[c4]     + hv[1] * wout_sh[c4 + 1]
                             + hv[2] * wout_sh[c4 + 2] + hv[3] * wout_sh[c4 + 3];
                    po += __shfl_xor_sync(0xffffffffu, po, 1);
                    po += __shfl_xor_sync(0xffffffffu, po, 2);
                    po += __shfl_xor_sync(0xffffffffu, po, 4);
                    if ((tid & 7) == 0) g_xp[t & 1][m0 + m][nt] = po;
                }
            }
            gbar(cG, rG, 32, epG);    // group-local: deps confined to this m-tile
        } // t  (final h in buf 0)

        gbar(&g_cntF, &g_relF, NCTA, epF);   // cross-group before global reads

        if (phase == 0) {
            // ---- features = sigmoid(hT @ Wenc^T + benc)  (permutation-aware) ----
            int d = bx * 16 + wid;
            if (d < 768) {
                int b = d / 3, e = d - 3 * b;
                const uint32_t* hpk = g_hpk[0] + (size_t)b * HDIM;
                const float* wp = Wenc + (size_t)e * HDIM;
                float s = 0.f;
                for (int k = lane * 4; k < HDIM; k += 128) {
                    uint4 w4 = __ldcg((const uint4*)(hpk + k));
                    int bk = k & ~15, t2 = (k >> 2) & 3;
                    s = fmaf(unpacksum(w4.x), wp[bk + 2 * t2],     s);
                    s = fmaf(unpacksum(w4.y), wp[bk + 2 * t2 + 1], s);
                    s = fmaf(unpacksum(w4.z), wp[bk + 2 * t2 + 8], s);
                    s = fmaf(unpacksum(w4.w), wp[bk + 2 * t2 + 9], s);
                }
#pragma unroll
                for (int o = 16; o; o >>= 1) s += __shfl_xor_sync(0xffffffffu, s, o);
                if (lane == 0) g_feat[b * 3 + e] = 1.f / (1.f + __expf(-(s + benc[e])));
            }
            gbar(&g_cntF, &g_relF, NCTA, epF);
            // ---- h0 = features @ Wdec^T + bdec -> buf 0 packed (permuted) ----
#pragma unroll
            for (int r = 0; r < 4; r++) {
                int i = bx * 2048 + r * NTHR + tid;
                int b = i >> 10, j = i & 1023;
                float v = bdec[j] + __ldcg(&g_feat[b * 3])     * Wdec[j * 3]
                                  + __ldcg(&g_feat[b * 3 + 1]) * Wdec[j * 3 + 1]
                                  + __ldcg(&g_feat[b * 3 + 2]) * Wdec[j * 3 + 2];
                g_hpk[0][((size_t)b << 10) | (j & ~15) | permslot(j & 15)] = packsplit(v);
            }
            gbar(&g_cntF, &g_relF, NCTA, epF);
        }
    } // phases

    // ---- tail: out[:, 511] = bout + sum xp[1] ----
    if (bx == 0 && tid < 256) {
        const float4* xp = (const float4*)&g_xp[1][tid][0];
        float s = bout0;
#pragma unroll
        for (int j = 0; j < 8; j++) {
            float4 v = __ldcg(xp + j);
            s += (v.x + v.y) + (v.z + v.w);
        }
        g_out[(size_t)tid * TLEN + (TLEN - 1)] = s;
    }
    gbar(&g_cntF, &g_relF, NCTA, epF);

    // ---- masked MSE numerator: 2 rows per CTA ----
    {
        int b = bx * 2 + (tid >> 8), l = tid & 255;
        int L = seqlen[b];
        float s = 0.f;
        for (int tt = l; tt < L; tt += 256) {
            float d = input[(size_t)b * TLEN + tt] - __ldcg(&g_out[(size_t)b * TLEN + tt]);
            s = fmaf(d, d, s);
        }
#pragma unroll
        for (int o = 16; o; o >>= 1) s += __shfl_xor_sync(0xffffffffu, s, o);
        if ((tid & 31) == 0) red_f[wid] = s;
        __syncthreads();
        if (tid == 0) {
            float tot = 0.f;
#pragma unroll
            for (int q = 0; q < 16; q++) tot += red_f[q];
            atomicAdd(&g_lossnum, tot);
        }
        __syncthreads();
    }
    gbar(&g_cntF, &g_relF, NCTA, epF);

    // ---- finalize loss (CTA 0) ----
    if (bx == 0) {
        if (tid < 256) red_f[tid] = (float)seqlen[tid];
        __syncthreads();
        for (int o = 128; o; o >>= 1) {
            if (tid < o && tid + o < 256) red_f[tid] += red_f[tid + o];
            __syncthreads();
        }
        if (tid == 0 && out_size > 0) dout[0] = g_lossnum / red_f[0];
    }

    // ---- pack (loss | input | output | features) ----
    {
        int chunk = (out_size + NCTA - 1) / NCTA;
        int lo = bx * chunk;
        int hi = lo + chunk; if (hi > out_size) hi = out_size;
        for (int i = lo + tid; i < hi; i += NTHR) {
            if (i == 0) continue;
            int j = i - 1;
            if (j < BATCH * TLEN) { dout[i] = input[j]; continue; }
            j -= BATCH * TLEN;
            if (j < BATCH * TLEN) { dout[i] = __ldcg(&g_out[j]); continue; }
            j -= BATCH * TLEN;
            if (j < BATCH * 3) { dout[i] = __ldcg(&g_feat[j]); continue; }
            dout[i] = 0.f;
        }
    }
}

extern "C" void kernel_launch(void* const* d_in, const int* in_sizes, int n_in,
                              void* d_out, int out_size) {
    const float* input  = (const float*)d_in[0];
    const int*   seqlen = (const int*)d_in[1];
    const float* Wih_e = (const float*)d_in[2];
    const float* Whh_e = (const float*)d_in[3];
    const float* bih_e = (const float*)d_in[4];
    const float* bhh_e = (const float*)d_in[5];
    const float* Wenc  = (const float*)d_in[6];
    const float* benc  = (const float*)d_in[7];
    const float* Wdec  = (const float*)d_in[8];
    const float* bdec  = (const float*)d_in[9];
    const float* Wih_d = (const float*)d_in[10];
    const float* Whh_d = (const float*)d_in[11];
    const float* bih_d = (const float*)d_in[12];
    const float* bhh_d = (const float*)d_in[13];
    const float* Wout  = (const float*)d_in[14];
    const float* bout  = (const float*)d_in[15];

    cudaFuncSetAttribute(persist_mma,
                         cudaFuncAttributeMaxDynamicSharedMemorySize, SMEM_BYTES);
    persist_mma<<<NCTA, NTHR, SMEM_BYTES>>>(
        input, seqlen, Wih_e, Whh_e, bih_e, bhh_e, Wenc, benc,
        Wdec, bdec, Wih_d, Whh_d, bih_d, bhh_d, Wout, bout,
        (float*)d_out, out_size);
}